// round 13
// baseline (speedup 1.0000x reference)
#include <cuda_runtime.h>
#include <cuda_fp16.h>
#include <mma.h>
#include <math.h>

using namespace nvcuda;

#define CC   64
#define HH   80
#define WW   160
#define HWSZ (HH * WW)      // 12800
#define BB   3
#define LL   4
#define EPSB 1e-5f
#define NEGV -1e30f

typedef unsigned int uint;

// Scratch:
//  g_Eh[b][pix][o/2]      conv partial (ego half, node[b,0]), channel-last, 128 ch, fp16
//  g_xth[b*4+j][pix][c/2] raw x transposed channel-last (64 ch, fp16) -> warped gathers
__device__ __align__(16) __half2 g_Eh[(size_t)BB * HWSZ * 64];        // 9.8 MB
__device__ __align__(16) __half2 g_xth[(size_t)BB * LL * HWSZ * 32];  // 19.7 MB

__device__ __forceinline__ float2 h2f(uint u) {
    return __half22float2(*reinterpret_cast<__half2*>(&u));
}

// ---------------- Kernel 1: fp16 transposes (A-jobs) + ego GEMM (E-jobs) ----------------
__global__ __launch_bounds__(256, 2) void disco_k1(const float* __restrict__ x,
                                                   const int* __restrict__ rec,
                                                   const float* __restrict__ w1) {
    __shared__ __align__(16) float Xs[64][133];
    __shared__ __align__(16) unsigned char sbuf[35840];
    half*  Xh    = (half*)sbuf;
    half*  Wh    = (half*)(sbuf + 18432);
    float* stage = (float*)sbuf;

    int job   = blockIdx.y;
    int ptile = blockIdx.x * 128;
    int r0 = rec[0], r1 = rec[1], r2 = rec[2];

    int t = threadIdx.x;
    bool isA = (job < 12);

    if (isA) {
        int b = job >> 2, j = job & 3;
        int rb   = (b == 0) ? r0 : ((b == 1) ? r1 : r2);
        if (j >= rb) return;
        int aoff = (b == 0) ? 0 : ((b == 1) ? r0 : (r0 + r1));
        const float* src = x + (size_t)(aoff + j) * CC * HWSZ;

        for (int i = t; i < 64 * 128; i += 256) {
            int c = i >> 7, p = i & 127;
            Xs[c][p] = src[c * HWSZ + ptile + p];
        }
        __syncthreads();

        __half2* xth = g_xth + (size_t)job * HWSZ * 32;
        for (int i = t; i < 128 * 32; i += 256) {
            int p = i >> 5, c2 = i & 31;
            xth[(size_t)(ptile + p) * 32 + c2] =
                __floats2half2_rn(Xs[2 * c2][p], Xs[2 * c2 + 1][p]);
        }
        return;
    }

    int b = job - 12;
    int aoff = (b == 0) ? 0 : ((b == 1) ? r0 : (r0 + r1));
    const float* src = x + (size_t)aoff * CC * HWSZ;
    __half2* dst = g_Eh + (size_t)b * HWSZ * 64;

    for (int i = t; i < 64 * 128; i += 256) {
        int c = i >> 7, p = i & 127;
        Xs[c][p] = src[c * HWSZ + ptile + p];
    }
    for (int i = t; i < 64 * 128; i += 256) {
        int c = i >> 7, o = i & 127;
        Wh[c * 136 + o] = __float2half(w1[(64 + c) * 128 + o]);
    }
    __syncthreads();
    for (int i = t; i < 128 * 64; i += 256) {
        int p = i >> 6, c = i & 63;
        Xh[p * 72 + c] = __float2half(Xs[c][p]);
    }
    __syncthreads();

    int w = t >> 5;
    wmma::fragment<wmma::accumulator, 16, 16, 16, float> acc[8];
#pragma unroll
    for (int j = 0; j < 8; j++) wmma::fill_fragment(acc[j], 0.0f);
#pragma unroll
    for (int k0 = 0; k0 < 64; k0 += 16) {
        wmma::fragment<wmma::matrix_a, 16, 16, 16, half, wmma::row_major> af;
        wmma::load_matrix_sync(af, Xh + (w * 16) * 72 + k0, 72);
#pragma unroll
        for (int j = 0; j < 8; j++) {
            wmma::fragment<wmma::matrix_b, 16, 16, 16, half, wmma::row_major> bf;
            wmma::load_matrix_sync(bf, Wh + k0 * 136 + j * 16, 136);
            wmma::mma_sync(acc[j], af, bf, acc[j]);
        }
    }
    __syncthreads();

#pragma unroll
    for (int hid = 0; hid < 2; hid++) {
#pragma unroll
        for (int j = 0; j < 4; j++)
            wmma::store_matrix_sync(stage + (w * 16) * 68 + j * 16, acc[hid * 4 + j], 68, wmma::mem_row_major);
        __syncthreads();
        for (int i = t; i < 128 * 32; i += 256) {
            int p = i >> 5, c2 = i & 31;
            __half2 hv = __floats2half2_rn(stage[p * 68 + 2 * c2], stage[p * 68 + 2 * c2 + 1]);
            dst[(size_t)(ptile + p) * 64 + hid * 32 + c2] = hv;
        }
        __syncthreads();
    }
}

// ---------------- Kernel 2: fused scores + ONLINE softmax-value + final MLP ------------
// grid = (200 pixel-tiles, 3 b); block 256; 3 blocks/SM
__global__ __launch_bounds__(256, 3) void disco_k2(
    const float* __restrict__ mask,
    const int* __restrict__ rec, const float* __restrict__ ptm,
    const float* __restrict__ w1,
    const float* __restrict__ cb1, const float* __restrict__ ga1,
    const float* __restrict__ be1, const float* __restrict__ rm1, const float* __restrict__ rv1,
    const float* __restrict__ w2, const float* __restrict__ cb2, const float* __restrict__ ga2,
    const float* __restrict__ be2, const float* __restrict__ rm2, const float* __restrict__ rv2,
    const float* __restrict__ w3, const float* __restrict__ cb3, const float* __restrict__ ga3,
    const float* __restrict__ be3, const float* __restrict__ rm3, const float* __restrict__ rv3,
    const float* __restrict__ w4, const float* __restrict__ cb4,
    const float* __restrict__ mlpw, const float* __restrict__ mlpb,
    float* __restrict__ out)
{
    __shared__ __align__(16) half  s_nb[64 * 72];        // warped nbr fp16, ONE slab (per-j)   9216 B
    __shared__ __align__(16) half  s_w1a[64 * 136];      // w1 nbr-half fp16                   17408 B
    __shared__ __align__(16) half  s_w2h[128 * 40];      // w2 fp16 [k][o] ld 40               10240 B
    __shared__ __align__(16) float u_buf[64 * 68];       // stage f32 -> h2 f32 -> s_mw        17408 B
    __shared__ __align__(16) uint  s_h1[64 * 68];        // h1 half2 per j -> s_u f32          17408 B
    __shared__ __align__(16) float s_f1s[128], s_f1b[128];
    __shared__ __align__(16) float s_f2s[32], s_f2b[32];
    __shared__ __align__(16) float s_w3[256];
    __shared__ __align__(16) float s_f3s[8], s_f3b[8], s_w4v[8];
    __shared__ float s_cb4v;
    __shared__ __align__(16) float s_com[64];
    __shared__ __align__(16) float s_mb[64];

    int b  = blockIdx.y;
    int rb = rec[b];
    int t  = threadIdx.x;
    int ptile = blockIdx.x * 64;

    if (t < 128) {
        float sc = ga1[t] * rsqrtf(rv1[t] + EPSB);
        s_f1s[t] = sc;
        s_f1b[t] = (cb1[t] - rm1[t]) * sc + be1[t];
    }
    for (int i = t; i < 64 * 128; i += 256) {
        int c = i >> 7, o = i & 127;
        s_w1a[c * 136 + o] = __float2half(w1[c * 128 + o]);
    }
    for (int i = t; i < 4096; i += 256) {
        int c = i >> 5, o = i & 31;
        s_w2h[c * 40 + o] = __float2half(w2[c * 32 + o]);
    }
    if (t < 32) {
        float sc = ga2[t] * rsqrtf(rv2[t] + EPSB);
        s_f2s[t] = sc;
        s_f2b[t] = (cb2[t] - rm2[t]) * sc + be2[t];
    }
    s_w3[t] = w3[t & 255];
    if (t < 8) {
        float sc = ga3[t] * rsqrtf(rv3[t] + EPSB);
        s_f3s[t] = sc;
        s_f3b[t] = (cb3[t] - rm3[t]) * sc + be3[t];
        s_w4v[t] = w4[t];
    }
    if (t == 0) s_cb4v = cb4[0];
    if (t < 64) s_mb[t] = mlpb[t];
    __syncthreads();

    const __half2* Eb = g_Eh + (size_t)b * HWSZ * 64;
    int w = t >> 5;

    // value-thread mapping: thread owns 16 channels of pixel pixv
    int pixv = t >> 2, cgv = t & 3;
    int pgv  = ptile + pixv;
    int hhv  = pgv / WW;
    int wpxv = pgv - hhv * WW;
    float gx = -1.0f + wpxv * (2.0f / (WW - 1));
    float gy = -1.0f + hhv  * (2.0f / (HH - 1));

    float uacc[16];
#pragma unroll
    for (int i = 0; i < 16; i++) uacc[i] = 0.0f;
    float den = 0.0f;

    for (int j = 0; j < rb; j++) {           // j >= rb contributes exp(NEGV)=0 -> skip
        int job = b * 4 + j;
        const float* th = ptm + (size_t)job * 24;
        float t00 = th[0], t01 = th[1], t02 = th[2];
        float t10 = th[3], t11 = th[4], t12 = th[5];
        const __half2* Xb = g_xth + (size_t)job * HWSZ * 32;
        const float*   Mb = mask  + (size_t)job * HWSZ;

        // interp coords for this thread's pixel under theta_j (shared by gather + value)
        float px = (t00 * gx + t01 * gy + t02 + 1.0f) * ((WW - 1) * 0.5f);
        float py = (t10 * gx + t11 * gy + t12 + 1.0f) * ((HH - 1) * 0.5f);
        float x0f = floorf(px), y0f = floorf(py);
        float wx = px - x0f, wy = py - y0f;
        int x0 = (int)x0f, y0 = (int)y0f;
        float wt4[4] = { (1.0f - wx) * (1.0f - wy), wx * (1.0f - wy),
                         (1.0f - wx) * wy,          wx * wy };

        // ---- Stage 1: gather warped raw x (16 ch/thread) -> s_nb; com from mask.
        {
            float acc[16];
#pragma unroll
            for (int i = 0; i < 16; i++) acc[i] = 0.0f;
            float comv = 0.0f;
#pragma unroll
            for (int tap = 0; tap < 4; tap++) {
                int xi = x0 + (tap & 1), yi = y0 + (tap >> 1);
                bool inb = (xi >= 0) && (xi < WW) && (yi >= 0) && (yi < HH);
                int xc = min(max(xi, 0), WW - 1);
                int yc = min(max(yi, 0), HH - 1);
                float tw = inb ? wt4[tap] : 0.0f;
                int rt = yc * WW + xc;
                if (cgv == 0) comv += tw * Mb[rt];
                const uint4* Xp = (const uint4*)(Xb + (size_t)rt * 32 + cgv * 8);
                uint4 v0 = Xp[0], v1 = Xp[1];
                float2 f;
                f = h2f(v0.x); acc[0]  = fmaf(tw, f.x, acc[0]);  acc[1]  = fmaf(tw, f.y, acc[1]);
                f = h2f(v0.y); acc[2]  = fmaf(tw, f.x, acc[2]);  acc[3]  = fmaf(tw, f.y, acc[3]);
                f = h2f(v0.z); acc[4]  = fmaf(tw, f.x, acc[4]);  acc[5]  = fmaf(tw, f.y, acc[5]);
                f = h2f(v0.w); acc[6]  = fmaf(tw, f.x, acc[6]);  acc[7]  = fmaf(tw, f.y, acc[7]);
                f = h2f(v1.x); acc[8]  = fmaf(tw, f.x, acc[8]);  acc[9]  = fmaf(tw, f.y, acc[9]);
                f = h2f(v1.y); acc[10] = fmaf(tw, f.x, acc[10]); acc[11] = fmaf(tw, f.y, acc[11]);
                f = h2f(v1.z); acc[12] = fmaf(tw, f.x, acc[12]); acc[13] = fmaf(tw, f.y, acc[13]);
                f = h2f(v1.w); acc[14] = fmaf(tw, f.x, acc[14]); acc[15] = fmaf(tw, f.y, acc[15]);
            }
            uint ow[8];
#pragma unroll
            for (int i = 0; i < 8; i++) {
                __half2 hp = __floats2half2_rn(acc[2 * i], acc[2 * i + 1]);
                ow[i] = *(uint*)&hp;
            }
            uint4* np = (uint4*)(s_nb + pixv * 72 + cgv * 16);
            uint4 wv0; wv0.x = ow[0]; wv0.y = ow[1]; wv0.z = ow[2]; wv0.w = ow[3];
            uint4 wv1; wv1.x = ow[4]; wv1.y = ow[5]; wv1.z = ow[6]; wv1.w = ow[7];
            np[0] = wv0;
            np[1] = wv1;
            if (cgv == 0) s_com[pixv] = comv;
        }
        __syncthreads();

        // ---- Stage 2: layer1 wmma [64 x 64] @ [64 x 128]
        {
            int mrow = (w & 3) * 16;
            int pgrp = w >> 2;
            int nbase = pgrp * 64;
            wmma::fragment<wmma::accumulator, 16, 16, 16, float> acc1[4];
#pragma unroll
            for (int jf = 0; jf < 4; jf++) wmma::fill_fragment(acc1[jf], 0.0f);
#pragma unroll
            for (int k0 = 0; k0 < 64; k0 += 16) {
                wmma::fragment<wmma::matrix_a, 16, 16, 16, half, wmma::row_major> af;
                wmma::load_matrix_sync(af, s_nb + mrow * 72 + k0, 72);
#pragma unroll
                for (int jf = 0; jf < 4; jf++) {
                    wmma::fragment<wmma::matrix_b, 16, 16, 16, half, wmma::row_major> bf;
                    wmma::load_matrix_sync(bf, s_w1a + k0 * 136 + nbase + jf * 16, 136);
                    wmma::mma_sync(acc1[jf], af, bf, acc1[jf]);
                }
            }

            // epilogue in 2 passes of 64 cols through u_buf
#pragma unroll
            for (int pass = 0; pass < 2; pass++) {
                __syncthreads();               // orders prior u_buf readers
                if (pgrp == pass) {
#pragma unroll
                    for (int jf = 0; jf < 4; jf++)
                        wmma::store_matrix_sync(u_buf + mrow * 68 + jf * 16, acc1[jf], 68, wmma::mem_row_major);
                }
                __syncthreads();
                for (int i = t; i < 64 * 32; i += 256) {
                    int pix = i >> 5, c2r = i & 31;
                    int c2 = pass * 32 + c2r;
                    uint eu = *(const uint*)(Eb + (size_t)(ptile + pix) * 64 + c2);
                    float2 ef = h2f(eu);
                    float a0 = u_buf[pix * 68 + 2 * c2r]     + ef.x;
                    float a1 = u_buf[pix * 68 + 2 * c2r + 1] + ef.y;
                    float2 sv = *(const float2*)&s_f1s[2 * c2];
                    float2 bv = *(const float2*)&s_f1b[2 * c2];
                    float h0 = fmaxf(0.0f, a0 * sv.x + bv.x);
                    float h1 = fmaxf(0.0f, a1 * sv.y + bv.y);
                    __half2 hp = __floats2half2_rn(h0, h1);
                    s_h1[pix * 68 + c2] = *(uint*)&hp;
                }
            }
        }
        __syncthreads();

        // ---- Stage 3: layer2 wmma [64 x 128] @ [128 x 32] -> u_buf f32 (ld 36)
        {
            const half* h1h = (const half*)s_h1;   // row-major [64][ld 136]
            int mrow = (w >> 1) * 16;
            int ncol = (w & 1) * 16;
            wmma::fragment<wmma::accumulator, 16, 16, 16, float> acc2;
            wmma::fill_fragment(acc2, 0.0f);
#pragma unroll
            for (int k0 = 0; k0 < 128; k0 += 16) {
                wmma::fragment<wmma::matrix_a, 16, 16, 16, half, wmma::row_major> af;
                wmma::fragment<wmma::matrix_b, 16, 16, 16, half, wmma::row_major> bf;
                wmma::load_matrix_sync(af, h1h + mrow * 136 + k0, 136);
                wmma::load_matrix_sync(bf, s_w2h + k0 * 40 + ncol, 40);
                wmma::mma_sync(acc2, af, bf, acc2);
            }
            wmma::store_matrix_sync(u_buf + mrow * 36 + ncol, acc2, 36, wmma::mem_row_major);
        }
        __syncthreads();

        // ---- Stage 4: layers 3/4 (bn2+relu fused) -> score; computed redundantly by
        // all 4 threads of each pixel (4-way broadcast reads, no extra sync), then
        // ONLINE accumulate value from the slab still resident in s_nb.
        {
            const float* s_h2f = u_buf;
            float p3[8];
#pragma unroll
            for (int o = 0; o < 8; o++) p3[o] = 0.0f;
#pragma unroll
            for (int k4 = 0; k4 < 8; k4++) {
                float4 hv = *(const float4*)&s_h2f[pixv * 36 + k4 * 4];
                float4 f2s = *(const float4*)&s_f2s[k4 * 4];
                float4 f2b = *(const float4*)&s_f2b[k4 * 4];
                float hk[4];
                hk[0] = fmaxf(0.0f, hv.x * f2s.x + f2b.x);
                hk[1] = fmaxf(0.0f, hv.y * f2s.y + f2b.y);
                hk[2] = fmaxf(0.0f, hv.z * f2s.z + f2b.z);
                hk[3] = fmaxf(0.0f, hv.w * f2s.w + f2b.w);
#pragma unroll
                for (int kk = 0; kk < 4; kk++) {
                    float4 wa = *(const float4*)&s_w3[(k4 * 4 + kk) * 8];
                    float4 wb = *(const float4*)&s_w3[(k4 * 4 + kk) * 8 + 4];
                    p3[0] = fmaf(hk[kk], wa.x, p3[0]);
                    p3[1] = fmaf(hk[kk], wa.y, p3[1]);
                    p3[2] = fmaf(hk[kk], wa.z, p3[2]);
                    p3[3] = fmaf(hk[kk], wa.w, p3[3]);
                    p3[4] = fmaf(hk[kk], wb.x, p3[4]);
                    p3[5] = fmaf(hk[kk], wb.y, p3[5]);
                    p3[6] = fmaf(hk[kk], wb.z, p3[6]);
                    p3[7] = fmaf(hk[kk], wb.w, p3[7]);
                }
            }
            float s4 = s_cb4v;
#pragma unroll
            for (int o = 0; o < 8; o++) {
                float h3 = fmaxf(0.0f, p3[o] * s_f3s[o] + s_f3b[o]);
                s4 = fmaf(h3, s_w4v[o], s4);
            }
            float comv = s_com[pixv];
            // score = (com==0) ? NEGV : relu(s4); e = exp(score); scores in [0, O(1)]
            // so no max-subtraction needed; j=0 always has com=1 -> den >= 1.
            float e = (comv == 0.0f) ? 0.0f : expf(fmaxf(0.0f, s4));
            den += e;
            float ec = e * comv;
            if (ec != 0.0f) {
                const uint4* np = (const uint4*)(s_nb + pixv * 72 + cgv * 16);
                uint4 v0 = np[0], v1 = np[1];
                uint vv[8] = { v0.x, v0.y, v0.z, v0.w, v1.x, v1.y, v1.z, v1.w };
#pragma unroll
                for (int i = 0; i < 8; i++) {
                    float2 f = h2f(vv[i]);
                    uacc[2 * i]     = fmaf(ec, f.x, uacc[2 * i]);
                    uacc[2 * i + 1] = fmaf(ec, f.y, uacc[2 * i + 1]);
                }
            }
        }
        __syncthreads();   // slab + u_buf reads done; reusable next j
    }

    // ---- finalize: u = uacc / den; load mlp_w; stage for final GEMM
    for (int i = t; i < 4096; i += 256) {
        int c = i >> 6, d = i & 63;
        u_buf[c * 68 + d] = mlpw[i];
    }
    float* s_u = (float*)s_h1;
    {
        float inv = 1.0f / den;
#pragma unroll
        for (int q = 0; q < 4; q++) {
            float4 v = make_float4(uacc[q * 4] * inv, uacc[q * 4 + 1] * inv,
                                   uacc[q * 4 + 2] * inv, uacc[q * 4 + 3] * inv);
            *(float4*)&s_u[pixv * 68 + cgv * 16 + q * 4] = v;
        }
    }
    __syncthreads();

    // ---- final MLP GEMM [64 x 64] @ [64 x 64], thread = 4 pix x 4 d
    {
        int tp = t >> 4, tn = t & 15;
        float acc[4][4];
#pragma unroll
        for (int p = 0; p < 4; p++)
#pragma unroll
            for (int d = 0; d < 4; d++) acc[p][d] = 0.0f;
#pragma unroll 4
        for (int k4 = 0; k4 < 16; k4++) {
            float4 uv[4];
#pragma unroll
            for (int p = 0; p < 4; p++)
                uv[p] = *(const float4*)&s_u[(tp * 4 + p) * 68 + k4 * 4];
            float4 wv[4];
#pragma unroll
            for (int kk = 0; kk < 4; kk++)
                wv[kk] = *(const float4*)&u_buf[(k4 * 4 + kk) * 68 + tn * 4];
#pragma unroll
            for (int p = 0; p < 4; p++) {
                acc[p][0] = fmaf(uv[p].x, wv[0].x, acc[p][0]);
                acc[p][1] = fmaf(uv[p].x, wv[0].y, acc[p][1]);
                acc[p][2] = fmaf(uv[p].x, wv[0].z, acc[p][2]);
                acc[p][3] = fmaf(uv[p].x, wv[0].w, acc[p][3]);
                acc[p][0] = fmaf(uv[p].y, wv[1].x, acc[p][0]);
                acc[p][1] = fmaf(uv[p].y, wv[1].y, acc[p][1]);
                acc[p][2] = fmaf(uv[p].y, wv[1].z, acc[p][2]);
                acc[p][3] = fmaf(uv[p].y, wv[1].w, acc[p][3]);
                acc[p][0] = fmaf(uv[p].z, wv[2].x, acc[p][0]);
                acc[p][1] = fmaf(uv[p].z, wv[2].y, acc[p][1]);
                acc[p][2] = fmaf(uv[p].z, wv[2].z, acc[p][2]);
                acc[p][3] = fmaf(uv[p].z, wv[2].w, acc[p][3]);
                acc[p][0] = fmaf(uv[p].w, wv[3].x, acc[p][0]);
                acc[p][1] = fmaf(uv[p].w, wv[3].y, acc[p][1]);
                acc[p][2] = fmaf(uv[p].w, wv[3].z, acc[p][2]);
                acc[p][3] = fmaf(uv[p].w, wv[3].w, acc[p][3]);
            }
        }
        float4 bias = *(const float4*)&s_mb[tn * 4];
        __syncthreads();
#pragma unroll
        for (int d = 0; d < 4; d++) {
            float bd = (d == 0) ? bias.x : (d == 1) ? bias.y : (d == 2) ? bias.z : bias.w;
            float4 ov = make_float4(acc[0][d] + bd, acc[1][d] + bd, acc[2][d] + bd, acc[3][d] + bd);
            *(float4*)&s_u[(tn * 4 + d) * 68 + tp * 4] = ov;
        }
    }
    __syncthreads();

    for (int i = t; i < 4096; i += 256) {
        int d = i >> 6, pp = i & 63;
        out[((size_t)b * CC + d) * HWSZ + ptile + pp] = s_u[d * 68 + pp];
    }
}

extern "C" void kernel_launch(void* const* d_in, const int* in_sizes, int n_in,
                              void* d_out, int out_size) {
    (void)in_sizes; (void)n_in; (void)out_size;
    const float* x    = (const float*)d_in[0];
    const float* mask = (const float*)d_in[1];
    const int*   rec  = (const int*)d_in[2];
    const float* ptm  = (const float*)d_in[3];
    const float* w1   = (const float*)d_in[4];
    const float* cb1  = (const float*)d_in[5];
    const float* ga1  = (const float*)d_in[6];
    const float* be1  = (const float*)d_in[7];
    const float* rm1  = (const float*)d_in[8];
    const float* rv1  = (const float*)d_in[9];
    const float* w2   = (const float*)d_in[10];
    const float* cb2  = (const float*)d_in[11];
    const float* ga2  = (const float*)d_in[12];
    const float* be2  = (const float*)d_in[13];
    const float* rm2  = (const float*)d_in[14];
    const float* rv2  = (const float*)d_in[15];
    const float* w3   = (const float*)d_in[16];
    const float* cb3  = (const float*)d_in[17];
    const float* ga3  = (const float*)d_in[18];
    const float* be3  = (const float*)d_in[19];
    const float* rm3  = (const float*)d_in[20];
    const float* rv3  = (const float*)d_in[21];
    const float* w4   = (const float*)d_in[22];
    const float* cb4  = (const float*)d_in[23];
    const float* mlpw = (const float*)d_in[24];
    const float* mlpb = (const float*)d_in[25];
    float* out = (float*)d_out;

    dim3 grid1(HWSZ / 128, 15);
    disco_k1<<<grid1, 256>>>(x, rec, w1);

    dim3 grid2(HWSZ / 64, BB);
    disco_k2<<<grid2, 256>>>(mask, rec, ptm, w1,
                             cb1, ga1, be1, rm1, rv1,
                             w2, cb2, ga2, be2, rm2, rv2,
                             w3, cb3, ga3, be3, rm3, rv3,
                             w4, cb4, mlpw, mlpb, out);
}

// round 16
// speedup vs baseline: 1.0728x; 1.0728x over previous
#include <cuda_runtime.h>
#include <cuda_fp16.h>
#include <mma.h>
#include <math.h>

using namespace nvcuda;

#define CC   64
#define HH   80
#define WW   160
#define HWSZ (HH * WW)      // 12800
#define BB   3
#define LL   4
#define EPSB 1e-5f
#define NEGV -1e30f

typedef unsigned int uint;

// Scratch:
//  g_Eh[b][pix][o/2]      conv partial (ego half, node[b,0]), channel-last, 128 ch, fp16
//  g_xth[b*4+j][pix][c/2] raw x transposed channel-last (64 ch, fp16) -> warped gathers
__device__ __align__(16) __half2 g_Eh[(size_t)BB * HWSZ * 64];        // 9.8 MB
__device__ __align__(16) __half2 g_xth[(size_t)BB * LL * HWSZ * 32];  // 19.7 MB

__device__ __forceinline__ float2 h2f(uint u) {
    return __half22float2(*reinterpret_cast<__half2*>(&u));
}

// ---------------- Kernel 1: fp16 transposes (A-jobs) + ego GEMM (E-jobs) ----------------
__global__ __launch_bounds__(256, 2) void disco_k1(const float* __restrict__ x,
                                                   const int* __restrict__ rec,
                                                   const float* __restrict__ w1) {
    __shared__ __align__(16) float Xs[64][133];
    __shared__ __align__(16) unsigned char sbuf[35840];
    half*  Xh    = (half*)sbuf;
    half*  Wh    = (half*)(sbuf + 18432);
    float* stage = (float*)sbuf;

    int job   = blockIdx.y;
    int ptile = blockIdx.x * 128;
    int r0 = rec[0], r1 = rec[1], r2 = rec[2];

    int t = threadIdx.x;
    bool isA = (job < 12);

    if (isA) {
        int b = job >> 2, j = job & 3;
        int rb   = (b == 0) ? r0 : ((b == 1) ? r1 : r2);
        if (j >= rb) return;
        int aoff = (b == 0) ? 0 : ((b == 1) ? r0 : (r0 + r1));
        const float* src = x + (size_t)(aoff + j) * CC * HWSZ;

        for (int i = t; i < 64 * 128; i += 256) {
            int c = i >> 7, p = i & 127;
            Xs[c][p] = src[c * HWSZ + ptile + p];
        }
        __syncthreads();

        __half2* xth = g_xth + (size_t)job * HWSZ * 32;
        for (int i = t; i < 128 * 32; i += 256) {
            int p = i >> 5, c2 = i & 31;
            xth[(size_t)(ptile + p) * 32 + c2] =
                __floats2half2_rn(Xs[2 * c2][p], Xs[2 * c2 + 1][p]);
        }
        return;
    }

    int b = job - 12;
    int aoff = (b == 0) ? 0 : ((b == 1) ? r0 : (r0 + r1));
    const float* src = x + (size_t)aoff * CC * HWSZ;
    __half2* dst = g_Eh + (size_t)b * HWSZ * 64;

    for (int i = t; i < 64 * 128; i += 256) {
        int c = i >> 7, p = i & 127;
        Xs[c][p] = src[c * HWSZ + ptile + p];
    }
    for (int i = t; i < 64 * 128; i += 256) {
        int c = i >> 7, o = i & 127;
        Wh[c * 136 + o] = __float2half(w1[(64 + c) * 128 + o]);
    }
    __syncthreads();
    for (int i = t; i < 128 * 64; i += 256) {
        int p = i >> 6, c = i & 63;
        Xh[p * 72 + c] = __float2half(Xs[c][p]);
    }
    __syncthreads();

    int w = t >> 5;
    wmma::fragment<wmma::accumulator, 16, 16, 16, float> acc[8];
#pragma unroll
    for (int j = 0; j < 8; j++) wmma::fill_fragment(acc[j], 0.0f);
#pragma unroll
    for (int k0 = 0; k0 < 64; k0 += 16) {
        wmma::fragment<wmma::matrix_a, 16, 16, 16, half, wmma::row_major> af;
        wmma::load_matrix_sync(af, Xh + (w * 16) * 72 + k0, 72);
#pragma unroll
        for (int j = 0; j < 8; j++) {
            wmma::fragment<wmma::matrix_b, 16, 16, 16, half, wmma::row_major> bf;
            wmma::load_matrix_sync(bf, Wh + k0 * 136 + j * 16, 136);
            wmma::mma_sync(acc[j], af, bf, acc[j]);
        }
    }
    __syncthreads();

#pragma unroll
    for (int hid = 0; hid < 2; hid++) {
#pragma unroll
        for (int j = 0; j < 4; j++)
            wmma::store_matrix_sync(stage + (w * 16) * 68 + j * 16, acc[hid * 4 + j], 68, wmma::mem_row_major);
        __syncthreads();
        for (int i = t; i < 128 * 32; i += 256) {
            int p = i >> 5, c2 = i & 31;
            __half2 hv = __floats2half2_rn(stage[p * 68 + 2 * c2], stage[p * 68 + 2 * c2 + 1]);
            dst[(size_t)(ptile + p) * 64 + hid * 32 + c2] = hv;
        }
        __syncthreads();
    }
}

// ---------------- Kernel 2: fused scores + softmax + value + final MLP ----------------
// grid = (200 pixel-tiles, 3 b); block 256; 2 blocks/SM (R11 config)
__global__ __launch_bounds__(256, 2) void disco_k2(
    const float* __restrict__ mask,
    const int* __restrict__ rec, const float* __restrict__ ptm,
    const float* __restrict__ w1,
    const float* __restrict__ cb1, const float* __restrict__ ga1,
    const float* __restrict__ be1, const float* __restrict__ rm1, const float* __restrict__ rv1,
    const float* __restrict__ w2, const float* __restrict__ cb2, const float* __restrict__ ga2,
    const float* __restrict__ be2, const float* __restrict__ rm2, const float* __restrict__ rv2,
    const float* __restrict__ w3, const float* __restrict__ cb3, const float* __restrict__ ga3,
    const float* __restrict__ be3, const float* __restrict__ rm3, const float* __restrict__ rv3,
    const float* __restrict__ w4, const float* __restrict__ cb4,
    const float* __restrict__ mlpw, const float* __restrict__ mlpb,
    float* __restrict__ out)
{
    __shared__ __align__(16) half  s_nb[4 * 64 * 72];    // warped nbr fp16 per j (persistent)
    __shared__ __align__(16) half  s_w1a[64 * 136];      // w1 nbr-half fp16
    __shared__ __align__(16) half  s_w2h[128 * 40];      // w2 fp16 [k][o] ld 40
    __shared__ __align__(16) float u_buf[64 * 68];       // warp-slices [8][16][34] -> h2 ld36 -> mlp_w ld68
    __shared__ __align__(16) uint  s_h1[64 * 68];        // h1 half2 per j -> s_u f32
    __shared__ __align__(16) float s_f1s[128], s_f1b[128];
    __shared__ __align__(16) float s_f2s[32], s_f2b[32];
    __shared__ __align__(16) float s_w3[256];
    __shared__ __align__(16) float s_f3s[8], s_f3b[8], s_w4v[8];
    __shared__ float s_cb4v;
    __shared__ __align__(16) float s_com[4][64];
    __shared__ __align__(16) float s_sj[4][64];
    __shared__ __align__(16) float s_mb[64];

    int b  = blockIdx.y;
    int rb = rec[b];
    int t  = threadIdx.x;
    int ptile = blockIdx.x * 64;

    if (t < 128) {
        float sc = ga1[t] * rsqrtf(rv1[t] + EPSB);
        s_f1s[t] = sc;
        s_f1b[t] = (cb1[t] - rm1[t]) * sc + be1[t];
    }
    for (int i = t; i < 64 * 128; i += 256) {
        int c = i >> 7, o = i & 127;
        s_w1a[c * 136 + o] = __float2half(w1[c * 128 + o]);
    }
    for (int i = t; i < 4096; i += 256) {
        int c = i >> 5, o = i & 31;
        s_w2h[c * 40 + o] = __float2half(w2[c * 32 + o]);
    }
    if (t < 32) {
        float sc = ga2[t] * rsqrtf(rv2[t] + EPSB);
        s_f2s[t] = sc;
        s_f2b[t] = (cb2[t] - rm2[t]) * sc + be2[t];
    }
    s_w3[t] = w3[t & 255];
    if (t < 8) {
        float sc = ga3[t] * rsqrtf(rv3[t] + EPSB);
        s_f3s[t] = sc;
        s_f3b[t] = (cb3[t] - rm3[t]) * sc + be3[t];
        s_w4v[t] = w4[t];
    }
    if (t == 0) s_cb4v = cb4[0];
    if (t < 64) s_mb[t] = mlpb[t];

    const __half2* Eb = g_Eh + (size_t)b * HWSZ * 64;

    // ================= GATHER PHASE: all 4 j's, no intervening barriers =================
    {
        int pix = t >> 2, cg = t & 3;
        int pg  = ptile + pix;
        int hh  = pg / WW;
        int wpx = pg - hh * WW;
        float gx = -1.0f + wpx * (2.0f / (WW - 1));
        float gy = -1.0f + hh  * (2.0f / (HH - 1));

        for (int j = 0; j < 4; j++) {
            if (j >= rb) {
                if (t < 64) { s_sj[j][t] = NEGV; s_com[j][t] = 0.0f; }
                continue;
            }
            int job = b * 4 + j;
            const float* th = ptm + (size_t)job * 24;
            float t00 = th[0], t01 = th[1], t02 = th[2];
            float t10 = th[3], t11 = th[4], t12 = th[5];
            const __half2* Xb = g_xth + (size_t)job * HWSZ * 32;
            const float*   Mb = mask  + (size_t)job * HWSZ;
            half* nbj = s_nb + j * 4608;

            float px = (t00 * gx + t01 * gy + t02 + 1.0f) * ((WW - 1) * 0.5f);
            float py = (t10 * gx + t11 * gy + t12 + 1.0f) * ((HH - 1) * 0.5f);
            float x0f = floorf(px), y0f = floorf(py);
            float wx = px - x0f, wy = py - y0f;
            int x0 = (int)x0f, y0 = (int)y0f;
            float wt4[4] = { (1.0f - wx) * (1.0f - wy), wx * (1.0f - wy),
                             (1.0f - wx) * wy,          wx * wy };
            float acc[16];
#pragma unroll
            for (int i = 0; i < 16; i++) acc[i] = 0.0f;
            float comv = 0.0f;
#pragma unroll
            for (int tap = 0; tap < 4; tap++) {
                int xi = x0 + (tap & 1), yi = y0 + (tap >> 1);
                bool inb = (xi >= 0) && (xi < WW) && (yi >= 0) && (yi < HH);
                int xc = min(max(xi, 0), WW - 1);
                int yc = min(max(yi, 0), HH - 1);
                float tw = inb ? wt4[tap] : 0.0f;
                int rt = yc * WW + xc;
                if (cg == 0) comv += tw * Mb[rt];
                const uint4* Xp = (const uint4*)(Xb + (size_t)rt * 32 + cg * 8);
                uint4 v0 = Xp[0], v1 = Xp[1];
                float2 f;
                f = h2f(v0.x); acc[0]  = fmaf(tw, f.x, acc[0]);  acc[1]  = fmaf(tw, f.y, acc[1]);
                f = h2f(v0.y); acc[2]  = fmaf(tw, f.x, acc[2]);  acc[3]  = fmaf(tw, f.y, acc[3]);
                f = h2f(v0.z); acc[4]  = fmaf(tw, f.x, acc[4]);  acc[5]  = fmaf(tw, f.y, acc[5]);
                f = h2f(v0.w); acc[6]  = fmaf(tw, f.x, acc[6]);  acc[7]  = fmaf(tw, f.y, acc[7]);
                f = h2f(v1.x); acc[8]  = fmaf(tw, f.x, acc[8]);  acc[9]  = fmaf(tw, f.y, acc[9]);
                f = h2f(v1.y); acc[10] = fmaf(tw, f.x, acc[10]); acc[11] = fmaf(tw, f.y, acc[11]);
                f = h2f(v1.z); acc[12] = fmaf(tw, f.x, acc[12]); acc[13] = fmaf(tw, f.y, acc[13]);
                f = h2f(v1.w); acc[14] = fmaf(tw, f.x, acc[14]); acc[15] = fmaf(tw, f.y, acc[15]);
            }
            uint ow[8];
#pragma unroll
            for (int i = 0; i < 8; i++) {
                __half2 hp = __floats2half2_rn(acc[2 * i], acc[2 * i + 1]);
                ow[i] = *(uint*)&hp;
            }
            uint4* np = (uint4*)(nbj + pix * 72 + cg * 16);
            uint4 wv0; wv0.x = ow[0]; wv0.y = ow[1]; wv0.z = ow[2]; wv0.w = ow[3];
            uint4 wv1; wv1.x = ow[4]; wv1.y = ow[5]; wv1.z = ow[6]; wv1.w = ow[7];
            np[0] = wv0;
            np[1] = wv1;
            if (cg == 0) s_com[j][pix] = comv;
        }
    }
    __syncthreads();

    // ================= COMPUTE PHASE: per valid j (3 block barriers per j) =================
    int w = t >> 5;
    int lane = t & 31;
    for (int j = 0; j < rb; j++) {
        half* nbj = s_nb + j * 4608;

        // ---- Stage 2: layer1 wmma [64 x 64] @ [64 x 128]; warp w: rows (w&3)*16, cols (w>>2)*64
        {
            int mrow = (w & 3) * 16;
            int nbase = (w >> 2) * 64;
            wmma::fragment<wmma::accumulator, 16, 16, 16, float> acc1[4];
#pragma unroll
            for (int jf = 0; jf < 4; jf++) wmma::fill_fragment(acc1[jf], 0.0f);
#pragma unroll
            for (int k0 = 0; k0 < 64; k0 += 16) {
                wmma::fragment<wmma::matrix_a, 16, 16, 16, half, wmma::row_major> af;
                wmma::load_matrix_sync(af, nbj + mrow * 72 + k0, 72);
#pragma unroll
                for (int jf = 0; jf < 4; jf++) {
                    wmma::fragment<wmma::matrix_b, 16, 16, 16, half, wmma::row_major> bf;
                    wmma::load_matrix_sync(bf, s_w1a + k0 * 136 + nbase + jf * 16, 136);
                    wmma::mma_sync(acc1[jf], af, bf, acc1[jf]);
                }
            }

            // ---- warp-local epilogue: stage frags through private u_buf slice [16][34]
            // (no block barriers; u_buf free per end-of-previous-j barrier)
            float* slice = u_buf + w * (16 * 34);
            int row   = mrow + (lane >> 1);
            int lcol  = (lane & 1) * 16;
#pragma unroll
            for (int chunk = 0; chunk < 2; chunk++) {
                wmma::store_matrix_sync(slice,      acc1[2 * chunk],     34, wmma::mem_row_major);
                wmma::store_matrix_sync(slice + 16, acc1[2 * chunk + 1], 34, wmma::mem_row_major);
                __syncwarp();
                int gc = nbase + chunk * 32 + lcol;          // global col start (16 cols)
                const float* sp = slice + (lane >> 1) * 34 + lcol;
                const uint4* Ep = (const uint4*)(Eb + (size_t)(ptile + row) * 64 + (gc >> 1));
                uint4 e0 = Ep[0], e1 = Ep[1];
                uint ev[8] = { e0.x, e0.y, e0.z, e0.w, e1.x, e1.y, e1.z, e1.w };
                uint ow[8];
#pragma unroll
                for (int i = 0; i < 8; i++) {
                    float2 ef = h2f(ev[i]);
                    float a0 = sp[2 * i]     + ef.x;
                    float a1 = sp[2 * i + 1] + ef.y;
                    float2 sv = *(const float2*)&s_f1s[gc + 2 * i];
                    float2 bv = *(const float2*)&s_f1b[gc + 2 * i];
                    float h0 = fmaxf(0.0f, a0 * sv.x + bv.x);
                    float h1 = fmaxf(0.0f, a1 * sv.y + bv.y);
                    __half2 hp = __floats2half2_rn(h0, h1);
                    ow[i] = *(uint*)&hp;
                }
                uint4 wv0; wv0.x = ow[0]; wv0.y = ow[1]; wv0.z = ow[2]; wv0.w = ow[3];
                uint4 wv1; wv1.x = ow[4]; wv1.y = ow[5]; wv1.z = ow[6]; wv1.w = ow[7];
                *(uint4*)&s_h1[row * 68 + (gc >> 1)]     = wv0;
                *(uint4*)&s_h1[row * 68 + (gc >> 1) + 4] = wv1;
                __syncwarp();       // slice reads done before next chunk's store
            }
        }
        __syncthreads();   // B1: s_h1 complete; u_buf slices free

        // ---- Stage 3: layer2 wmma [64 x 128] @ [128 x 32] -> u_buf f32 (ld 36)
        {
            const half* h1h = (const half*)s_h1;   // row-major [64][ld 136]
            int mrow = (w >> 1) * 16;
            int ncol = (w & 1) * 16;
            wmma::fragment<wmma::accumulator, 16, 16, 16, float> acc2;
            wmma::fill_fragment(acc2, 0.0f);
#pragma unroll
            for (int k0 = 0; k0 < 128; k0 += 16) {
                wmma::fragment<wmma::matrix_a, 16, 16, 16, half, wmma::row_major> af;
                wmma::fragment<wmma::matrix_b, 16, 16, 16, half, wmma::row_major> bf;
                wmma::load_matrix_sync(af, h1h + mrow * 136 + k0, 136);
                wmma::load_matrix_sync(bf, s_w2h + k0 * 40 + ncol, 40);
                wmma::mma_sync(acc2, af, bf, acc2);
            }
            wmma::store_matrix_sync(u_buf + mrow * 36 + ncol, acc2, 36, wmma::mem_row_major);
        }
        __syncthreads();   // B2: layer2 output ready

        // ---- Stage 4: layers 3/4 with fused bn2+relu -> score
        if (t < 64) {
            const float* s_h2f = u_buf;
            int pix = t;
            float p3[8];
#pragma unroll
            for (int o = 0; o < 8; o++) p3[o] = 0.0f;
#pragma unroll
            for (int k4 = 0; k4 < 8; k4++) {
                float4 hv = *(const float4*)&s_h2f[pix * 36 + k4 * 4];
                float4 f2s = *(const float4*)&s_f2s[k4 * 4];
                float4 f2b = *(const float4*)&s_f2b[k4 * 4];
                float hk[4];
                hk[0] = fmaxf(0.0f, hv.x * f2s.x + f2b.x);
                hk[1] = fmaxf(0.0f, hv.y * f2s.y + f2b.y);
                hk[2] = fmaxf(0.0f, hv.z * f2s.z + f2b.z);
                hk[3] = fmaxf(0.0f, hv.w * f2s.w + f2b.w);
#pragma unroll
                for (int kk = 0; kk < 4; kk++) {
                    float4 wa = *(const float4*)&s_w3[(k4 * 4 + kk) * 8];
                    float4 wb = *(const float4*)&s_w3[(k4 * 4 + kk) * 8 + 4];
                    p3[0] = fmaf(hk[kk], wa.x, p3[0]);
                    p3[1] = fmaf(hk[kk], wa.y, p3[1]);
                    p3[2] = fmaf(hk[kk], wa.z, p3[2]);
                    p3[3] = fmaf(hk[kk], wa.w, p3[3]);
                    p3[4] = fmaf(hk[kk], wb.x, p3[4]);
                    p3[5] = fmaf(hk[kk], wb.y, p3[5]);
                    p3[6] = fmaf(hk[kk], wb.z, p3[6]);
                    p3[7] = fmaf(hk[kk], wb.w, p3[7]);
                }
            }
            float s4 = s_cb4v;
#pragma unroll
            for (int o = 0; o < 8; o++) {
                float h3 = fmaxf(0.0f, p3[o] * s_f3s[o] + s_f3b[o]);
                s4 = fmaf(h3, s_w4v[o], s4);
            }
            float comv = s_com[j][pix];
            s_sj[j][pix] = (comv == 0.0f) ? NEGV : fmaxf(0.0f, s4);
        }
        __syncthreads();   // B3: u_buf free for next j's epilogue slices
    }

    // ---- load mlp_w into u_buf [c][d] ld 68
    for (int i = t; i < 4096; i += 256) {
        int c = i >> 6, d = i & 63;
        u_buf[c * 68 + d] = mlpw[i];
    }

    // ---- softmax + value-combine from smem -> s_u (aliases s_h1)
    float* s_u = (float*)s_h1;
    {
        int pix = t >> 2, cg = t & 3;
        float sj[4], cj[4];
#pragma unroll
        for (int j = 0; j < 4; j++) { sj[j] = s_sj[j][pix]; cj[j] = s_com[j][pix]; }
        float m = fmaxf(fmaxf(sj[0], sj[1]), fmaxf(sj[2], sj[3]));
        float ex[4], ssum = 0.0f;
#pragma unroll
        for (int j = 0; j < 4; j++) { ex[j] = expf(sj[j] - m); ssum += ex[j]; }
        float inv = 1.0f / ssum;

        float u[16];
#pragma unroll
        for (int i = 0; i < 16; i++) u[i] = 0.0f;
        for (int j = 0; j < 4; j++) {
            if (j >= rb) continue;
            float wgt = ex[j] * inv * cj[j];
            if (wgt == 0.0f) continue;
            const uint4* np = (const uint4*)(s_nb + j * 4608 + pix * 72 + cg * 16);
            uint4 v0 = np[0], v1 = np[1];
            uint vv[8] = { v0.x, v0.y, v0.z, v0.w, v1.x, v1.y, v1.z, v1.w };
#pragma unroll
            for (int i = 0; i < 8; i++) {
                float2 f = h2f(vv[i]);
                u[2 * i]     = fmaf(wgt, f.x, u[2 * i]);
                u[2 * i + 1] = fmaf(wgt, f.y, u[2 * i + 1]);
            }
        }
#pragma unroll
        for (int q = 0; q < 4; q++) {
            float4 v = make_float4(u[q * 4], u[q * 4 + 1], u[q * 4 + 2], u[q * 4 + 3]);
            *(float4*)&s_u[pix * 68 + cg * 16 + q * 4] = v;
        }
    }
    __syncthreads();

    // ---- final MLP GEMM [64 x 64] @ [64 x 64], thread = 4 pix x 4 d
    {
        int tp = t >> 4, tn = t & 15;
        float acc[4][4];
#pragma unroll
        for (int p = 0; p < 4; p++)
#pragma unroll
            for (int d = 0; d < 4; d++) acc[p][d] = 0.0f;
#pragma unroll 4
        for (int k4 = 0; k4 < 16; k4++) {
            float4 uv[4];
#pragma unroll
            for (int p = 0; p < 4; p++)
                uv[p] = *(const float4*)&s_u[(tp * 4 + p) * 68 + k4 * 4];
            float4 wv[4];
#pragma unroll
            for (int kk = 0; kk < 4; kk++)
                wv[kk] = *(const float4*)&u_buf[(k4 * 4 + kk) * 68 + tn * 4];
#pragma unroll
            for (int p = 0; p < 4; p++) {
                acc[p][0] = fmaf(uv[p].x, wv[0].x, acc[p][0]);
                acc[p][1] = fmaf(uv[p].x, wv[0].y, acc[p][1]);
                acc[p][2] = fmaf(uv[p].x, wv[0].z, acc[p][2]);
                acc[p][3] = fmaf(uv[p].x, wv[0].w, acc[p][3]);
                acc[p][0] = fmaf(uv[p].y, wv[1].x, acc[p][0]);
                acc[p][1] = fmaf(uv[p].y, wv[1].y, acc[p][1]);
                acc[p][2] = fmaf(uv[p].y, wv[1].z, acc[p][2]);
                acc[p][3] = fmaf(uv[p].y, wv[1].w, acc[p][3]);
                acc[p][0] = fmaf(uv[p].z, wv[2].x, acc[p][0]);
                acc[p][1] = fmaf(uv[p].z, wv[2].y, acc[p][1]);
                acc[p][2] = fmaf(uv[p].z, wv[2].z, acc[p][2]);
                acc[p][3] = fmaf(uv[p].z, wv[2].w, acc[p][3]);
                acc[p][0] = fmaf(uv[p].w, wv[3].x, acc[p][0]);
                acc[p][1] = fmaf(uv[p].w, wv[3].y, acc[p][1]);
                acc[p][2] = fmaf(uv[p].w, wv[3].z, acc[p][2]);
                acc[p][3] = fmaf(uv[p].w, wv[3].w, acc[p][3]);
            }
        }
        float4 bias = *(const float4*)&s_mb[tn * 4];
        __syncthreads();
#pragma unroll
        for (int d = 0; d < 4; d++) {
            float bd = (d == 0) ? bias.x : (d == 1) ? bias.y : (d == 2) ? bias.z : bias.w;
            float4 ov = make_float4(acc[0][d] + bd, acc[1][d] + bd, acc[2][d] + bd, acc[3][d] + bd);
            *(float4*)&s_u[(tn * 4 + d) * 68 + tp * 4] = ov;
        }
    }
    __syncthreads();

    for (int i = t; i < 4096; i += 256) {
        int d = i >> 6, pp = i & 63;
        out[((size_t)b * CC + d) * HWSZ + ptile + pp] = s_u[d * 68 + pp];
    }
}

extern "C" void kernel_launch(void* const* d_in, const int* in_sizes, int n_in,
                              void* d_out, int out_size) {
    (void)in_sizes; (void)n_in; (void)out_size;
    const float* x    = (const float*)d_in[0];
    const float* mask = (const float*)d_in[1];
    const int*   rec  = (const int*)d_in[2];
    const float* ptm  = (const float*)d_in[3];
    const float* w1   = (const float*)d_in[4];
    const float* cb1  = (const float*)d_in[5];
    const float* ga1  = (const float*)d_in[6];
    const float* be1  = (const float*)d_in[7];
    const float* rm1  = (const float*)d_in[8];
    const float* rv1  = (const float*)d_in[9];
    const float* w2   = (const float*)d_in[10];
    const float* cb2  = (const float*)d_in[11];
    const float* ga2  = (const float*)d_in[12];
    const float* be2  = (const float*)d_in[13];
    const float* rm2  = (const float*)d_in[14];
    const float* rv2  = (const float*)d_in[15];
    const float* w3   = (const float*)d_in[16];
    const float* cb3  = (const float*)d_in[17];
    const float* ga3  = (const float*)d_in[18];
    const float* be3  = (const float*)d_in[19];
    const float* rm3  = (const float*)d_in[20];
    const float* rv3  = (const float*)d_in[21];
    const float* w4   = (const float*)d_in[22];
    const float* cb4  = (const float*)d_in[23];
    const float* mlpw = (const float*)d_in[24];
    const float* mlpb = (const float*)d_in[25];
    float* out = (float*)d_out;

    dim3 grid1(HWSZ / 128, 15);
    disco_k1<<<grid1, 256>>>(x, rec, w1);

    dim3 grid2(HWSZ / 64, BB);
    disco_k2<<<grid2, 256>>>(mask, rec, ptm, w1,
                             cb1, ga1, be1, rm1, rv1,
                             w2, cb2, ga2, be2, rm2, rv2,
                             w3, cb3, ga3, be3, rm3, rv3,
                             w4, cb4, mlpw, mlpb, out);
}

// round 17
// speedup vs baseline: 1.1527x; 1.0745x over previous
#include <cuda_runtime.h>
#include <cuda_fp16.h>
#include <mma.h>
#include <math.h>

using namespace nvcuda;

#define CC   64
#define HH   80
#define WW   160
#define HWSZ (HH * WW)      // 12800
#define BB   3
#define LL   4
#define EPSB 1e-5f
#define NEGV -1e30f

typedef unsigned int uint;

// Scratch:
//  g_Eh[b][pix][o/2]      conv partial (ego half, node[b,0]), channel-last, 128 ch, fp16
//  g_xth[b*4+j][pix][c/2] raw x transposed channel-last (64 ch, fp16) -> warped gathers
__device__ __align__(16) __half2 g_Eh[(size_t)BB * HWSZ * 64];        // 9.8 MB
__device__ __align__(16) __half2 g_xth[(size_t)BB * LL * HWSZ * 32];  // 19.7 MB

__device__ __forceinline__ float2 h2f(uint u) {
    return __half22float2(*reinterpret_cast<__half2*>(&u));
}
__device__ __forceinline__ uint smem_u32(const void* p) {
    return (uint)__cvta_generic_to_shared(p);
}
__device__ __forceinline__ void ldm_x4(uint& r0, uint& r1, uint& r2, uint& r3, uint addr) {
    asm volatile("ldmatrix.sync.aligned.m8n8.x4.shared.b16 {%0,%1,%2,%3}, [%4];"
                 : "=r"(r0), "=r"(r1), "=r"(r2), "=r"(r3) : "r"(addr));
}
__device__ __forceinline__ void ldm_x2_t(uint& r0, uint& r1, uint addr) {
    asm volatile("ldmatrix.sync.aligned.m8n8.x2.trans.shared.b16 {%0,%1}, [%2];"
                 : "=r"(r0), "=r"(r1) : "r"(addr));
}
__device__ __forceinline__ void mma16816(float d[4], const uint a[4], const uint b[2]) {
    asm volatile("mma.sync.aligned.m16n8k16.row.col.f32.f16.f16.f32 "
                 "{%0,%1,%2,%3}, {%4,%5,%6,%7}, {%8,%9}, {%0,%1,%2,%3};"
                 : "+f"(d[0]), "+f"(d[1]), "+f"(d[2]), "+f"(d[3])
                 : "r"(a[0]), "r"(a[1]), "r"(a[2]), "r"(a[3]), "r"(b[0]), "r"(b[1]));
}

// ---------------- Kernel 1: fp16 transposes (A-jobs) + ego GEMM (E-jobs) ----------------
__global__ __launch_bounds__(256, 2) void disco_k1(const float* __restrict__ x,
                                                   const int* __restrict__ rec,
                                                   const float* __restrict__ w1) {
    __shared__ __align__(16) float Xs[64][133];
    __shared__ __align__(16) unsigned char sbuf[35840];
    half*  Xh    = (half*)sbuf;
    half*  Wh    = (half*)(sbuf + 18432);
    float* stage = (float*)sbuf;

    int job   = blockIdx.y;
    int ptile = blockIdx.x * 128;
    int r0 = rec[0], r1 = rec[1], r2 = rec[2];

    int t = threadIdx.x;
    bool isA = (job < 12);

    if (isA) {
        int b = job >> 2, j = job & 3;
        int rb   = (b == 0) ? r0 : ((b == 1) ? r1 : r2);
        if (j >= rb) return;
        int aoff = (b == 0) ? 0 : ((b == 1) ? r0 : (r0 + r1));
        const float* src = x + (size_t)(aoff + j) * CC * HWSZ;

        for (int i = t; i < 64 * 128; i += 256) {
            int c = i >> 7, p = i & 127;
            Xs[c][p] = src[c * HWSZ + ptile + p];
        }
        __syncthreads();

        __half2* xth = g_xth + (size_t)job * HWSZ * 32;
        for (int i = t; i < 128 * 32; i += 256) {
            int p = i >> 5, c2 = i & 31;
            xth[(size_t)(ptile + p) * 32 + c2] =
                __floats2half2_rn(Xs[2 * c2][p], Xs[2 * c2 + 1][p]);
        }
        return;
    }

    int b = job - 12;
    int aoff = (b == 0) ? 0 : ((b == 1) ? r0 : (r0 + r1));
    const float* src = x + (size_t)aoff * CC * HWSZ;
    __half2* dst = g_Eh + (size_t)b * HWSZ * 64;

    for (int i = t; i < 64 * 128; i += 256) {
        int c = i >> 7, p = i & 127;
        Xs[c][p] = src[c * HWSZ + ptile + p];
    }
    for (int i = t; i < 64 * 128; i += 256) {
        int c = i >> 7, o = i & 127;
        Wh[c * 136 + o] = __float2half(w1[(64 + c) * 128 + o]);
    }
    __syncthreads();
    for (int i = t; i < 128 * 64; i += 256) {
        int p = i >> 6, c = i & 63;
        Xh[p * 72 + c] = __float2half(Xs[c][p]);
    }
    __syncthreads();

    int w = t >> 5;
    wmma::fragment<wmma::accumulator, 16, 16, 16, float> acc[8];
#pragma unroll
    for (int j = 0; j < 8; j++) wmma::fill_fragment(acc[j], 0.0f);
#pragma unroll
    for (int k0 = 0; k0 < 64; k0 += 16) {
        wmma::fragment<wmma::matrix_a, 16, 16, 16, half, wmma::row_major> af;
        wmma::load_matrix_sync(af, Xh + (w * 16) * 72 + k0, 72);
#pragma unroll
        for (int j = 0; j < 8; j++) {
            wmma::fragment<wmma::matrix_b, 16, 16, 16, half, wmma::row_major> bf;
            wmma::load_matrix_sync(bf, Wh + k0 * 136 + j * 16, 136);
            wmma::mma_sync(acc[j], af, bf, acc[j]);
        }
    }
    __syncthreads();

#pragma unroll
    for (int hid = 0; hid < 2; hid++) {
#pragma unroll
        for (int j = 0; j < 4; j++)
            wmma::store_matrix_sync(stage + (w * 16) * 68 + j * 16, acc[hid * 4 + j], 68, wmma::mem_row_major);
        __syncthreads();
        for (int i = t; i < 128 * 32; i += 256) {
            int p = i >> 5, c2 = i & 31;
            __half2 hv = __floats2half2_rn(stage[p * 68 + 2 * c2], stage[p * 68 + 2 * c2 + 1]);
            dst[(size_t)(ptile + p) * 64 + hid * 32 + c2] = hv;
        }
        __syncthreads();
    }
}

// ---------------- Kernel 2: fused scores + softmax + value + final MLP ----------------
// grid = (200 pixel-tiles, 3 b); block 256; 2 blocks/SM (R11 config, register epilogue)
__global__ __launch_bounds__(256, 2) void disco_k2(
    const float* __restrict__ mask,
    const int* __restrict__ rec, const float* __restrict__ ptm,
    const float* __restrict__ w1,
    const float* __restrict__ cb1, const float* __restrict__ ga1,
    const float* __restrict__ be1, const float* __restrict__ rm1, const float* __restrict__ rv1,
    const float* __restrict__ w2, const float* __restrict__ cb2, const float* __restrict__ ga2,
    const float* __restrict__ be2, const float* __restrict__ rm2, const float* __restrict__ rv2,
    const float* __restrict__ w3, const float* __restrict__ cb3, const float* __restrict__ ga3,
    const float* __restrict__ be3, const float* __restrict__ rm3, const float* __restrict__ rv3,
    const float* __restrict__ w4, const float* __restrict__ cb4,
    const float* __restrict__ mlpw, const float* __restrict__ mlpb,
    float* __restrict__ out)
{
    __shared__ __align__(16) half  s_nb[4 * 64 * 72];    // warped nbr fp16 per j (persistent)
    __shared__ __align__(16) half  s_w1a[64 * 136];      // w1 nbr-half fp16
    __shared__ __align__(16) half  s_w2h[128 * 40];      // w2 fp16 [k][o] ld 40
    __shared__ __align__(16) float u_buf[64 * 68];       // h2 ld36 -> mlp_w ld68
    __shared__ __align__(16) uint  s_h1[64 * 68];        // h1 half2 per j -> s_u f32
    __shared__ __align__(16) float s_f1s[128], s_f1b[128];
    __shared__ __align__(16) float s_f2s[32], s_f2b[32];
    __shared__ __align__(16) float s_w3[256];
    __shared__ __align__(16) float s_f3s[8], s_f3b[8], s_w4v[8];
    __shared__ float s_cb4v;
    __shared__ __align__(16) float s_com[4][64];
    __shared__ __align__(16) float s_sj[4][64];
    __shared__ __align__(16) float s_mb[64];

    int b  = blockIdx.y;
    int rb = rec[b];
    int t  = threadIdx.x;
    int ptile = blockIdx.x * 64;

    if (t < 128) {
        float sc = ga1[t] * rsqrtf(rv1[t] + EPSB);
        s_f1s[t] = sc;
        s_f1b[t] = (cb1[t] - rm1[t]) * sc + be1[t];
    }
    for (int i = t; i < 64 * 128; i += 256) {
        int c = i >> 7, o = i & 127;
        s_w1a[c * 136 + o] = __float2half(w1[c * 128 + o]);
    }
    for (int i = t; i < 4096; i += 256) {
        int c = i >> 5, o = i & 31;
        s_w2h[c * 40 + o] = __float2half(w2[c * 32 + o]);
    }
    if (t < 32) {
        float sc = ga2[t] * rsqrtf(rv2[t] + EPSB);
        s_f2s[t] = sc;
        s_f2b[t] = (cb2[t] - rm2[t]) * sc + be2[t];
    }
    s_w3[t] = w3[t & 255];
    if (t < 8) {
        float sc = ga3[t] * rsqrtf(rv3[t] + EPSB);
        s_f3s[t] = sc;
        s_f3b[t] = (cb3[t] - rm3[t]) * sc + be3[t];
        s_w4v[t] = w4[t];
    }
    if (t == 0) s_cb4v = cb4[0];
    if (t < 64) s_mb[t] = mlpb[t];

    const __half2* Eb = g_Eh + (size_t)b * HWSZ * 64;

    // ================= GATHER PHASE: all 4 j's, no intervening barriers =================
    {
        int pix = t >> 2, cg = t & 3;
        int pg  = ptile + pix;
        int hh  = pg / WW;
        int wpx = pg - hh * WW;
        float gx = -1.0f + wpx * (2.0f / (WW - 1));
        float gy = -1.0f + hh  * (2.0f / (HH - 1));

        for (int j = 0; j < 4; j++) {
            if (j >= rb) {
                if (t < 64) { s_sj[j][t] = NEGV; s_com[j][t] = 0.0f; }
                continue;
            }
            int job = b * 4 + j;
            const float* th = ptm + (size_t)job * 24;
            float t00 = th[0], t01 = th[1], t02 = th[2];
            float t10 = th[3], t11 = th[4], t12 = th[5];
            const __half2* Xb = g_xth + (size_t)job * HWSZ * 32;
            const float*   Mb = mask  + (size_t)job * HWSZ;
            half* nbj = s_nb + j * 4608;

            float px = (t00 * gx + t01 * gy + t02 + 1.0f) * ((WW - 1) * 0.5f);
            float py = (t10 * gx + t11 * gy + t12 + 1.0f) * ((HH - 1) * 0.5f);
            float x0f = floorf(px), y0f = floorf(py);
            float wx = px - x0f, wy = py - y0f;
            int x0 = (int)x0f, y0 = (int)y0f;
            float wt4[4] = { (1.0f - wx) * (1.0f - wy), wx * (1.0f - wy),
                             (1.0f - wx) * wy,          wx * wy };
            float acc[16];
#pragma unroll
            for (int i = 0; i < 16; i++) acc[i] = 0.0f;
            float comv = 0.0f;
#pragma unroll
            for (int tap = 0; tap < 4; tap++) {
                int xi = x0 + (tap & 1), yi = y0 + (tap >> 1);
                bool inb = (xi >= 0) && (xi < WW) && (yi >= 0) && (yi < HH);
                int xc = min(max(xi, 0), WW - 1);
                int yc = min(max(yi, 0), HH - 1);
                float tw = inb ? wt4[tap] : 0.0f;
                int rt = yc * WW + xc;
                if (cg == 0) comv += tw * Mb[rt];
                const uint4* Xp = (const uint4*)(Xb + (size_t)rt * 32 + cg * 8);
                uint4 v0 = Xp[0], v1 = Xp[1];
                float2 f;
                f = h2f(v0.x); acc[0]  = fmaf(tw, f.x, acc[0]);  acc[1]  = fmaf(tw, f.y, acc[1]);
                f = h2f(v0.y); acc[2]  = fmaf(tw, f.x, acc[2]);  acc[3]  = fmaf(tw, f.y, acc[3]);
                f = h2f(v0.z); acc[4]  = fmaf(tw, f.x, acc[4]);  acc[5]  = fmaf(tw, f.y, acc[5]);
                f = h2f(v0.w); acc[6]  = fmaf(tw, f.x, acc[6]);  acc[7]  = fmaf(tw, f.y, acc[7]);
                f = h2f(v1.x); acc[8]  = fmaf(tw, f.x, acc[8]);  acc[9]  = fmaf(tw, f.y, acc[9]);
                f = h2f(v1.y); acc[10] = fmaf(tw, f.x, acc[10]); acc[11] = fmaf(tw, f.y, acc[11]);
                f = h2f(v1.z); acc[12] = fmaf(tw, f.x, acc[12]); acc[13] = fmaf(tw, f.y, acc[13]);
                f = h2f(v1.w); acc[14] = fmaf(tw, f.x, acc[14]); acc[15] = fmaf(tw, f.y, acc[15]);
            }
            uint ow[8];
#pragma unroll
            for (int i = 0; i < 8; i++) {
                __half2 hp = __floats2half2_rn(acc[2 * i], acc[2 * i + 1]);
                ow[i] = *(uint*)&hp;
            }
            uint4* np = (uint4*)(nbj + pix * 72 + cg * 16);
            uint4 wv0; wv0.x = ow[0]; wv0.y = ow[1]; wv0.z = ow[2]; wv0.w = ow[3];
            uint4 wv1; wv1.x = ow[4]; wv1.y = ow[5]; wv1.z = ow[6]; wv1.w = ow[7];
            np[0] = wv0;
            np[1] = wv1;
            if (cg == 0) s_com[j][pix] = comv;
        }
    }
    __syncthreads();

    // ================= COMPUTE PHASE: per valid j (3 block barriers per j) =================
    int w = t >> 5;
    int lane = t & 31;
    for (int j = 0; j < rb; j++) {
        half* nbj = s_nb + j * 4608;

        // ---- Stage 2: layer1 via mma.sync m16n8k16, register-resident epilogue -> s_h1
        // warp w: m-rows mrow..mrow+15 (mrow=(w&3)*16), n-cols nbase..nbase+63 (nbase=(w>>2)*64)
        {
            int mrow  = (w & 3) * 16;
            int nbase = (w >> 2) * 64;
            float dacc[8][4];
#pragma unroll
            for (int nt = 0; nt < 8; nt++)
#pragma unroll
                for (int i = 0; i < 4; i++) dacc[nt][i] = 0.0f;

            // ldmatrix lane addressing
            uint a_row = mrow + (lane & 15);
            uint a_off = (lane >> 4) << 3;               // +8 halfs for col tiles 8-15
#pragma unroll
            for (int k0 = 0; k0 < 64; k0 += 16) {
                uint af[4];
                ldm_x4(af[0], af[1], af[2], af[3],
                       smem_u32(nbj + a_row * 72 + k0 + a_off));
                uint b_rowaddr = smem_u32(s_w1a + (k0 + (lane & 15)) * 136 + nbase);
#pragma unroll
                for (int nt = 0; nt < 8; nt++) {
                    uint bf[2];
                    ldm_x2_t(bf[0], bf[1], b_rowaddr + nt * 16);   // +8 halfs
                    mma16816(dacc[nt], af, bf);
                }
            }

            // register epilogue: d0,d1 -> (row = lane>>2, cols c0,c0+1); d2,d3 -> row+8
            int r0w = mrow + (lane >> 2);
            int cqd = 2 * (lane & 3);
#pragma unroll
            for (int nt = 0; nt < 8; nt++) {
                int c0 = nbase + nt * 8 + cqd;           // even
                float2 sv = *(const float2*)&s_f1s[c0];
                float2 bv = *(const float2*)&s_f1b[c0];
#pragma unroll
                for (int half_ = 0; half_ < 2; half_++) {
                    int r = r0w + half_ * 8;
                    float2 ef = h2f(*(const uint*)(Eb + (size_t)(ptile + r) * 64 + (c0 >> 1)));
                    float d0 = dacc[nt][2 * half_];
                    float d1 = dacc[nt][2 * half_ + 1];
                    float h0 = fmaxf(0.0f, (d0 + ef.x) * sv.x + bv.x);
                    float h1 = fmaxf(0.0f, (d1 + ef.y) * sv.y + bv.y);
                    __half2 hp = __floats2half2_rn(h0, h1);
                    s_h1[r * 68 + (c0 >> 1)] = *(uint*)&hp;
                }
            }
        }
        __syncthreads();   // B1: s_h1 complete

        // ---- Stage 3: layer2 wmma [64 x 128] @ [128 x 32] -> u_buf f32 (ld 36)
        {
            const half* h1h = (const half*)s_h1;   // row-major [64][ld 136]
            int mrow = (w >> 1) * 16;
            int ncol = (w & 1) * 16;
            wmma::fragment<wmma::accumulator, 16, 16, 16, float> acc2;
            wmma::fill_fragment(acc2, 0.0f);
#pragma unroll
            for (int k0 = 0; k0 < 128; k0 += 16) {
                wmma::fragment<wmma::matrix_a, 16, 16, 16, half, wmma::row_major> af;
                wmma::fragment<wmma::matrix_b, 16, 16, 16, half, wmma::row_major> bf;
                wmma::load_matrix_sync(af, h1h + mrow * 136 + k0, 136);
                wmma::load_matrix_sync(bf, s_w2h + k0 * 40 + ncol, 40);
                wmma::mma_sync(acc2, af, bf, acc2);
            }
            wmma::store_matrix_sync(u_buf + mrow * 36 + ncol, acc2, 36, wmma::mem_row_major);
        }
        __syncthreads();   // B2: layer2 output ready

        // ---- Stage 4: layers 3/4 with fused bn2+relu -> score
        if (t < 64) {
            const float* s_h2f = u_buf;
            int pix = t;
            float p3[8];
#pragma unroll
            for (int o = 0; o < 8; o++) p3[o] = 0.0f;
#pragma unroll
            for (int k4 = 0; k4 < 8; k4++) {
                float4 hv = *(const float4*)&s_h2f[pix * 36 + k4 * 4];
                float4 f2s = *(const float4*)&s_f2s[k4 * 4];
                float4 f2b = *(const float4*)&s_f2b[k4 * 4];
                float hk[4];
                hk[0] = fmaxf(0.0f, hv.x * f2s.x + f2b.x);
                hk[1] = fmaxf(0.0f, hv.y * f2s.y + f2b.y);
                hk[2] = fmaxf(0.0f, hv.z * f2s.z + f2b.z);
                hk[3] = fmaxf(0.0f, hv.w * f2s.w + f2b.w);
#pragma unroll
                for (int kk = 0; kk < 4; kk++) {
                    float4 wa = *(const float4*)&s_w3[(k4 * 4 + kk) * 8];
                    float4 wb = *(const float4*)&s_w3[(k4 * 4 + kk) * 8 + 4];
                    p3[0] = fmaf(hk[kk], wa.x, p3[0]);
                    p3[1] = fmaf(hk[kk], wa.y, p3[1]);
                    p3[2] = fmaf(hk[kk], wa.z, p3[2]);
                    p3[3] = fmaf(hk[kk], wa.w, p3[3]);
                    p3[4] = fmaf(hk[kk], wb.x, p3[4]);
                    p3[5] = fmaf(hk[kk], wb.y, p3[5]);
                    p3[6] = fmaf(hk[kk], wb.z, p3[6]);
                    p3[7] = fmaf(hk[kk], wb.w, p3[7]);
                }
            }
            float s4 = s_cb4v;
#pragma unroll
            for (int o = 0; o < 8; o++) {
                float h3 = fmaxf(0.0f, p3[o] * s_f3s[o] + s_f3b[o]);
                s4 = fmaf(h3, s_w4v[o], s4);
            }
            float comv = s_com[j][pix];
            s_sj[j][pix] = (comv == 0.0f) ? NEGV : fmaxf(0.0f, s4);
        }
        __syncthreads();   // B3: u_buf free; s_h1 free for next j
    }

    // ---- load mlp_w into u_buf [c][d] ld 68
    for (int i = t; i < 4096; i += 256) {
        int c = i >> 6, d = i & 63;
        u_buf[c * 68 + d] = mlpw[i];
    }

    // ---- softmax + value-combine from smem -> s_u (aliases s_h1)
    float* s_u = (float*)s_h1;
    {
        int pix = t >> 2, cg = t & 3;
        float sj[4], cj[4];
#pragma unroll
        for (int j = 0; j < 4; j++) { sj[j] = s_sj[j][pix]; cj[j] = s_com[j][pix]; }
        float m = fmaxf(fmaxf(sj[0], sj[1]), fmaxf(sj[2], sj[3]));
        float ex[4], ssum = 0.0f;
#pragma unroll
        for (int j = 0; j < 4; j++) { ex[j] = expf(sj[j] - m); ssum += ex[j]; }
        float inv = 1.0f / ssum;

        float u[16];
#pragma unroll
        for (int i = 0; i < 16; i++) u[i] = 0.0f;
        for (int j = 0; j < 4; j++) {
            if (j >= rb) continue;
            float wgt = ex[j] * inv * cj[j];
            if (wgt == 0.0f) continue;
            const uint4* np = (const uint4*)(s_nb + j * 4608 + pix * 72 + cg * 16);
            uint4 v0 = np[0], v1 = np[1];
            uint vv[8] = { v0.x, v0.y, v0.z, v0.w, v1.x, v1.y, v1.z, v1.w };
#pragma unroll
            for (int i = 0; i < 8; i++) {
                float2 f = h2f(vv[i]);
                u[2 * i]     = fmaf(wgt, f.x, u[2 * i]);
                u[2 * i + 1] = fmaf(wgt, f.y, u[2 * i + 1]);
            }
        }
#pragma unroll
        for (int q = 0; q < 4; q++) {
            float4 v = make_float4(u[q * 4], u[q * 4 + 1], u[q * 4 + 2], u[q * 4 + 3]);
            *(float4*)&s_u[pix * 68 + cg * 16 + q * 4] = v;
        }
    }
    __syncthreads();

    // ---- final MLP GEMM [64 x 64] @ [64 x 64], thread = 4 pix x 4 d
    {
        int tp = t >> 4, tn = t & 15;
        float acc[4][4];
#pragma unroll
        for (int p = 0; p < 4; p++)
#pragma unroll
            for (int d = 0; d < 4; d++) acc[p][d] = 0.0f;
#pragma unroll 4
        for (int k4 = 0; k4 < 16; k4++) {
            float4 uv[4];
#pragma unroll
            for (int p = 0; p < 4; p++)
                uv[p] = *(const float4*)&s_u[(tp * 4 + p) * 68 + k4 * 4];
            float4 wv[4];
#pragma unroll
            for (int kk = 0; kk < 4; kk++)
                wv[kk] = *(const float4*)&u_buf[(k4 * 4 + kk) * 68 + tn * 4];
#pragma unroll
            for (int p = 0; p < 4; p++) {
                acc[p][0] = fmaf(uv[p].x, wv[0].x, acc[p][0]);
                acc[p][1] = fmaf(uv[p].x, wv[0].y, acc[p][1]);
                acc[p][2] = fmaf(uv[p].x, wv[0].z, acc[p][2]);
                acc[p][3] = fmaf(uv[p].x, wv[0].w, acc[p][3]);
                acc[p][0] = fmaf(uv[p].y, wv[1].x, acc[p][0]);
                acc[p][1] = fmaf(uv[p].y, wv[1].y, acc[p][1]);
                acc[p][2] = fmaf(uv[p].y, wv[1].z, acc[p][2]);
                acc[p][3] = fmaf(uv[p].y, wv[1].w, acc[p][3]);
                acc[p][0] = fmaf(uv[p].z, wv[2].x, acc[p][0]);
                acc[p][1] = fmaf(uv[p].z, wv[2].y, acc[p][1]);
                acc[p][2] = fmaf(uv[p].z, wv[2].z, acc[p][2]);
                acc[p][3] = fmaf(uv[p].z, wv[2].w, acc[p][3]);
                acc[p][0] = fmaf(uv[p].w, wv[3].x, acc[p][0]);
                acc[p][1] = fmaf(uv[p].w, wv[3].y, acc[p][1]);
                acc[p][2] = fmaf(uv[p].w, wv[3].z, acc[p][2]);
                acc[p][3] = fmaf(uv[p].w, wv[3].w, acc[p][3]);
            }
        }
        float4 bias = *(const float4*)&s_mb[tn * 4];
        __syncthreads();
#pragma unroll
        for (int d = 0; d < 4; d++) {
            float bd = (d == 0) ? bias.x : (d == 1) ? bias.y : (d == 2) ? bias.z : bias.w;
            float4 ov = make_float4(acc[0][d] + bd, acc[1][d] + bd, acc[2][d] + bd, acc[3][d] + bd);
            *(float4*)&s_u[(tn * 4 + d) * 68 + tp * 4] = ov;
        }
    }
    __syncthreads();

    for (int i = t; i < 4096; i += 256) {
        int d = i >> 6, pp = i & 63;
        out[((size_t)b * CC + d) * HWSZ + ptile + pp] = s_u[d * 68 + pp];
    }
}

extern "C" void kernel_launch(void* const* d_in, const int* in_sizes, int n_in,
                              void* d_out, int out_size) {
    (void)in_sizes; (void)n_in; (void)out_size;
    const float* x    = (const float*)d_in[0];
    const float* mask = (const float*)d_in[1];
    const int*   rec  = (const int*)d_in[2];
    const float* ptm  = (const float*)d_in[3];
    const float* w1   = (const float*)d_in[4];
    const float* cb1  = (const float*)d_in[5];
    const float* ga1  = (const float*)d_in[6];
    const float* be1  = (const float*)d_in[7];
    const float* rm1  = (const float*)d_in[8];
    const float* rv1  = (const float*)d_in[9];
    const float* w2   = (const float*)d_in[10];
    const float* cb2  = (const float*)d_in[11];
    const float* ga2  = (const float*)d_in[12];
    const float* be2  = (const float*)d_in[13];
    const float* rm2  = (const float*)d_in[14];
    const float* rv2  = (const float*)d_in[15];
    const float* w3   = (const float*)d_in[16];
    const float* cb3  = (const float*)d_in[17];
    const float* ga3  = (const float*)d_in[18];
    const float* be3  = (const float*)d_in[19];
    const float* rm3  = (const float*)d_in[20];
    const float* rv3  = (const float*)d_in[21];
    const float* w4   = (const float*)d_in[22];
    const float* cb4  = (const float*)d_in[23];
    const float* mlpw = (const float*)d_in[24];
    const float* mlpb = (const float*)d_in[25];
    float* out = (float*)d_out;

    dim3 grid1(HWSZ / 128, 15);
    disco_k1<<<grid1, 256>>>(x, rec, w1);

    dim3 grid2(HWSZ / 64, BB);
    disco_k2<<<grid2, 256>>>(mask, rec, ptm, w1,
                             cb1, ga1, be1, rm1, rv1,
                             w2, cb2, ga2, be2, rm2, rv2,
                             w3, cb3, ga3, be3, rm3, rv3,
                             w4, cb4, mlpw, mlpb, out);
}